// round 7
// baseline (speedup 1.0000x reference)
#include <cuda_runtime.h>
#include <cuda_bf16.h>
#include <math.h>
#include <stdint.h>

// ---------------- problem constants ----------------
#define Bv     64
#define Lv     256
#define Ev     1600
#define Pv     100
#define Nv     400          // P*4 (no padding)
#define NTILE  80           // per-CTA n tile
#define MTILE  64           // per-CTA m tile
#define Mv     16384        // B*L
#define Kv     1600
#define NCH    50           // Kv/32

// output layout (floats)
#define OFF_D0   6400
#define OFF_D1   556928
#define OFF_D2   1084928
#define OFF_FC   1606592

// ---------------- device scratch ----------------
static __device__ float g_Yt[(size_t)Nv * Mv];   // Y^T [n][m]
static __device__ float g_S[Mv];                 // row sum of squares
static __device__ float g_P2[Pv];                // proto sum of squares
// B bf16 chunked: [kc][n(400)][32 k]  (64B per row-chunk)
static __device__ __align__(16) unsigned char g_Bc[(size_t)NCH * Nv * 64];

// ---------------- smem layout (per CTA, dynamic) ----------------
//  buf s (s=0,1) at s*11520:
//    A tile: 64 rows * 80B @ +0     (5120 B)
//    B tile: 80 rows * 80B @ +5120  (6400 B)
#define BUFSTRIDE 11520
#define BOFF      5120
#define SMEM_DYN  (2 * BUFSTRIDE)

__device__ __forceinline__ uint32_t s2u(const void* p) {
    uint32_t a;
    asm("{ .reg .u64 t; cvta.to.shared.u64 t, %1; cvt.u32.u64 %0, t; }" : "=r"(a) : "l"(p));
    return a;
}

#define CP_ASYNC16(dst, src) \
    asm volatile("cp.async.cg.shared.global [%0], [%1], 16;" :: "r"(dst), "l"(src) : "memory")
#define CP_COMMIT() asm volatile("cp.async.commit_group;" ::: "memory")
#define CP_WAIT(n)  asm volatile("cp.async.wait_group %0;" :: "n"(n) : "memory")

#define LDM_X4(r0, r1, r2, r3, a) \
    asm volatile("ldmatrix.sync.aligned.m8n8.x4.shared.b16 {%0,%1,%2,%3}, [%4];" \
                 : "=r"(r0), "=r"(r1), "=r"(r2), "=r"(r3) : "r"(a))
#define LDM_X2(r0, r1, a) \
    asm volatile("ldmatrix.sync.aligned.m8n8.x2.shared.b16 {%0,%1}, [%2];" \
                 : "=r"(r0), "=r"(r1) : "r"(a))

#define MMA16816(d, a, b) \
    asm volatile("mma.sync.aligned.m16n8k16.row.col.f32.bf16.bf16.f32 " \
                 "{%0,%1,%2,%3}, {%4,%5,%6,%7}, {%8,%9}, {%0,%1,%2,%3};" \
                 : "+f"((d)[0]), "+f"((d)[1]), "+f"((d)[2]), "+f"((d)[3]) \
                 : "r"((a)[0]), "r"((a)[1]), "r"((a)[2]), "r"((a)[3]), \
                   "r"((b)[0]), "r"((b)[1]))

// ---------------- prep: reorganize protolayer, P2, zero FC ----------------
__global__ void prep_b_kernel(const float* __restrict__ proto, float* __restrict__ out) {
    int p = blockIdx.x;                                     // 0..99
    if (p == 0 && threadIdx.x < 2 * Bv) out[OFF_FC + threadIdx.x] = 0.0f;
    __shared__ float red[256];
    float s = 0.0f;
    for (int i = threadIdx.x; i < Ev * 4; i += 256) {
        int e = i >> 2, t = i & 3;
        float v = proto[(size_t)p * (Ev * 4) + i];
        s += v * v;
        int n = 4 * p + t;
        int kc = e >> 5, dk = e & 31;
        *reinterpret_cast<__nv_bfloat16*>(
            g_Bc + ((size_t)kc * Nv + n) * 64 + dk * 2) = __float2bfloat16(v);
    }
    red[threadIdx.x] = s;
    __syncthreads();
    for (int st = 128; st > 0; st >>= 1) {
        if (threadIdx.x < st) red[threadIdx.x] += red[threadIdx.x + st];
        __syncthreads();
    }
    if (threadIdx.x == 0) g_P2[p] = red[0];
}

// ---------------- A convert + STS: 8 floats -> one 16B bf16 store ----------------
__device__ __forceinline__ void sts_a2(char* dst, float4 a, float4 b, float& ssq) {
    ssq += a.x * a.x + a.y * a.y + a.z * a.z + a.w * a.w
         + b.x * b.x + b.y * b.y + b.z * b.z + b.w * b.w;
    __nv_bfloat162 p0 = __floats2bfloat162_rn(a.x, a.y);
    __nv_bfloat162 p1 = __floats2bfloat162_rn(a.z, a.w);
    __nv_bfloat162 p2 = __floats2bfloat162_rn(b.x, b.y);
    __nv_bfloat162 p3 = __floats2bfloat162_rn(b.z, b.w);
    uint4 w;
    w.x = *reinterpret_cast<uint32_t*>(&p0);
    w.y = *reinterpret_cast<uint32_t*>(&p1);
    w.z = *reinterpret_cast<uint32_t*>(&p2);
    w.w = *reinterpret_cast<uint32_t*>(&p3);
    *reinterpret_cast<uint4*>(dst) = w;
}

// ---------------- HMMA GEMM: Yt[n][m] = sum_k X[m][k]*W[k][n] ----------------
// grid (5, 256): 64x80 tile per CTA; 8 warps (4M x 2N), warp tile 16x40.
__global__ void __launch_bounds__(256, 4)
gemm_mma_kernel(const float* __restrict__ X) {
    extern __shared__ __align__(128) char smem[];
    const uint32_t sb = s2u(smem);
    const int tid  = threadIdx.x;
    const int wid  = tid >> 5;
    const int lane = tid & 31;
    const int nb = blockIdx.x;              // 0..4
    const int m0 = blockIdx.y * MTILE;
    const int n0 = nb * NTILE;

    const int m_warp = (wid >> 1) * 16;     // 0,16,32,48
    const int n_warp = (wid & 1) * 40;      // 0,40

    // ---- per-lane ldmatrix base offsets (within a buffer) ----
    const uint32_t aA = sb + (uint32_t)(m_warp + (lane & 15)) * 80 + (lane >> 4) * 16;
    const uint32_t aB4 = sb + BOFF +
        (uint32_t)(n_warp + ((lane >> 4) << 3) + (lane & 7)) * 80 + ((lane >> 3) & 1) * 16;
    const int l15 = lane & 15;
    const uint32_t aB2 = sb + BOFF +
        (uint32_t)(n_warp + 32 + (l15 & 7)) * 80 + ((l15 >> 3) & 1) * 16;

    // ---- A global source: this thread's 8-float strip per chunk ----
    const int r = tid >> 2;                 // row 0..63
    const int h = tid & 3;                  // k quarter (8 floats)
    const float4* xs = reinterpret_cast<const float4*>(X + (size_t)(m0 + r) * Kv) + h * 2;
    char* aDst0 = smem + r * 80 + h * 16;   // + buf*BUFSTRIDE

    float acc[5][4];
    #pragma unroll
    for (int j = 0; j < 5; ++j)
        #pragma unroll
        for (int q = 0; q < 4; ++q) acc[j][q] = 0.0f;

    float ssq = 0.0f;
    float4 rA0, rA1;

    // ---- prologue: chunk 0 -> buf0; prefetch chunk 1 ----
    {
        rA0 = xs[0]; rA1 = xs[1];
        sts_a2(aDst0, rA0, rA1, ssq);
        const char* bsrc = (const char*)(g_Bc + (size_t)n0 * 64);   // kc=0
        for (int i = tid; i < 320; i += 256)
            CP_ASYNC16(sb + BOFF + (i >> 2) * 80 + (i & 3) * 16,
                       bsrc + (i >> 2) * 64 + (i & 3) * 16);
        CP_COMMIT();
        rA0 = xs[8]; rA1 = xs[9];
        const char* bsrc1 = (const char*)(g_Bc + ((size_t)Nv + n0) * 64);
        for (int i = tid; i < 320; i += 256)
            CP_ASYNC16(sb + BUFSTRIDE + BOFF + (i >> 2) * 80 + (i & 3) * 16,
                       bsrc1 + (i >> 2) * 64 + (i & 3) * 16);
        CP_COMMIT();
        CP_WAIT(1);
        __syncthreads();
    }

    for (int kc = 0; kc < NCH; ++kc) {
        const uint32_t bo = (kc & 1) ? BUFSTRIDE : 0;
        // ---- compute chunk kc ----
        #pragma unroll
        for (int ks = 0; ks < 2; ++ks) {
            uint32_t afr[4];
            LDM_X4(afr[0], afr[1], afr[2], afr[3], aA + bo + ks * 32);
            uint32_t bfr[5][2];
            #pragma unroll
            for (int p = 0; p < 2; ++p)
                LDM_X4(bfr[2 * p][0], bfr[2 * p][1], bfr[2 * p + 1][0], bfr[2 * p + 1][1],
                       aB4 + bo + p * 1280 + ks * 32);
            LDM_X2(bfr[4][0], bfr[4][1], aB2 + bo + ks * 32);
            #pragma unroll
            for (int nf = 0; nf < 5; ++nf)
                MMA16816(acc[nf], afr, bfr[nf]);
        }
        // ---- stage chunk kc+1 / prefetch kc+2 ----
        if (kc < NCH - 1) {
            __syncthreads();
            const uint32_t bn = (kc & 1) ? 0 : BUFSTRIDE;   // next buffer
            sts_a2(aDst0 + bn, rA0, rA1, ssq);
            if (kc < NCH - 2) {
                rA0 = xs[(kc + 2) * 8];
                rA1 = xs[(kc + 2) * 8 + 1];
                const char* bsrc = (const char*)(g_Bc + ((size_t)(kc + 2) * Nv + n0) * 64);
                for (int i = tid; i < 320; i += 256)
                    CP_ASYNC16(sb + bo + BOFF + (i >> 2) * 80 + (i & 3) * 16,
                               bsrc + (i >> 2) * 64 + (i & 3) * 16);
                CP_COMMIT();
                CP_WAIT(1);
            } else {
                CP_WAIT(0);
            }
            __syncthreads();
        }
    }

    // ---- fused sumsq (nb==0 only): reduce across the 4 threads of a row ----
    if (nb == 0) {
        float tot = ssq + __shfl_xor_sync(0xffffffffu, ssq, 1);
        tot += __shfl_xor_sync(0xffffffffu, tot, 2);
        if (h == 0) g_S[m0 + r] = tot;
    }

    // ---- epilogue: acc -> g_Yt[n][m]  (no n guard: N=400 exact) ----
    {
        const int mbase = m0 + m_warp + (lane >> 2);
        #pragma unroll
        for (int nf = 0; nf < 5; ++nf) {
            const int nbase = n0 + n_warp + nf * 8 + 2 * (lane & 3);
            g_Yt[(size_t)nbase * Mv + mbase]           = acc[nf][0];
            g_Yt[(size_t)(nbase + 1) * Mv + mbase]     = acc[nf][1];
            g_Yt[(size_t)nbase * Mv + mbase + 8]       = acc[nf][2];
            g_Yt[(size_t)(nbase + 1) * Mv + mbase + 8] = acc[nf][3];
        }
    }
}

// ---------------- distances + per-(b,p) min + fused fc (atomicAdd) ----------------
__global__ void __launch_bounds__(256)
dist_kernel(float* __restrict__ out, const float* __restrict__ fcw) {
    int idx  = blockIdx.x * 8 + (threadIdx.x >> 5);   // (b,p), grid 800 -> 6400
    int lane = threadIdx.x & 31;
    int p = idx % Pv;
    int b = idx / Pv;
    int g = (p < 34) ? 0 : (p < 67) ? 1 : 2;
    int d = g + 1;
    int Lout = Lv - 3 * d;                             // 253/250/247
    int pbase = (g == 0) ? 0 : (g == 1) ? 34 : 67;
    int nf = (g == 0) ? 34 : 33;
    size_t dbase = (g == 0) ? OFF_D0 : (g == 1) ? OFF_D1 : OFF_D2;
    float* orow = out + dbase + ((size_t)b * nf + (p - pbase)) * Lout;

    const float* y0 = g_Yt + (size_t)(p * 4) * Mv + b * Lv;
    const float* s0 = g_S + b * Lv;
    const float p2 = g_P2[p];

    float mn = 3.402823466e38f;
    #pragma unroll
    for (int it = 0; it < 8; ++it) {
        int l = lane + it * 32;
        if (l < Lout) {
            float xp = 0.0f, x2 = 0.0f;
            #pragma unroll
            for (int k = 0; k < 4; ++k) {
                xp += y0[(size_t)k * Mv + l + k * d];
                x2 += s0[l + k * d];
            }
            float val = sqrtf(fabsf(x2 - 2.0f * xp + p2));
            orow[l] = val;
            mn = fminf(mn, val);
        }
    }
    #pragma unroll
    for (int o = 16; o > 0; o >>= 1) mn = fminf(mn, __shfl_xor_sync(0xffffffffu, mn, o));
    if (lane == 0) {
        out[b * Pv + p] = mn;
        atomicAdd(out + OFF_FC + b * 2 + 0, mn * fcw[p]);
        atomicAdd(out + OFF_FC + b * 2 + 1, mn * fcw[Pv + p]);
    }
}

// ---------------- launch ----------------
extern "C" void kernel_launch(void* const* d_in, const int* in_sizes, int n_in,
                              void* d_out, int out_size) {
    const float* emb   = (const float*)d_in[0];   // [64,256,1600]
    const float* proto = (const float*)d_in[1];   // [100,1600,4]
    const float* fcw   = (const float*)d_in[2];   // [2,100]
    float* out = (float*)d_out;

    prep_b_kernel<<<100, 256>>>(proto, out);
    gemm_mma_kernel<<<dim3(5, 256), 256, SMEM_DYN>>>(emb);
    dist_kernel<<<800, 256>>>(out, fcw);
}